// round 8
// baseline (speedup 1.0000x reference)
#include <cuda_runtime.h>

// Fully fused, parallel per-block prelude, 8 samples/thread (single wave).
//
// Math (verified rounds 2-3):
//   h_j  = tanh(W1[j,:].x + b1[j]);  th_j = h_j + qw[0,j]
//   z    = K1*cos(th1)cos(th2)cos(th3) - K2*sin(th0)sin(th1)
//          K1 = cos(qw[2,0]),  K2 = sin(qw[2,0])*cos(qw[1,0])*cos(qw[1,1])
//   out  = relu(z*W2 + b2) @ W3^T + b3
//
// tanh(u) = (1-e)*rcp(1+e), e = ex2(-2*log2e*u): sign-correct, clamp-free.

__global__ void __launch_bounds__(256) qnn_fused(
    const float4* __restrict__ x4, float2* __restrict__ out, int stride,
    const float* __restrict__ W1, const float* __restrict__ b1,
    const float* __restrict__ qw, const float* __restrict__ W2,
    const float* __restrict__ b2, const float* __restrict__ W3,
    const float* __restrict__ b3)
{
    __shared__ float4 sc[11];
    {
        float* v = reinterpret_cast<float*>(sc);
        const float SC = -2.8853900817779268f;   // -2*log2(e)
        int t = threadIdx.x;
        // 44 independent one-value producers; no serial chain, one barrier.
        if (t < 16)      v[t] = SC * W1[t];                 // W1s rows 0..3
        else if (t < 20) v[t] = SC * b1[t - 16];            // b1s
        else if (t < 24) v[t] = qw[t - 20];                 // qw[0,i]
        else if (t == 24) v[24] = __cosf(qw[8]);            // K1
        else if (t == 25) v[25] = __sinf(qw[8]) * __cosf(qw[4]) * __cosf(qw[5]); // K2
        else if (t < 28) v[t] = b3[t - 26];                 // b3
        else if (t < 32) v[t] = W2[t - 28];                 // W2
        else if (t < 36) v[t] = b2[t - 32];                 // b2
        else if (t < 44) v[t] = W3[t - 36];                 // W3 (2x4)
    }
    __syncthreads();

    const float4 r0 = sc[0], r1 = sc[1], r2 = sc[2], r3 = sc[3], bs = sc[4];
    const float4 q0 = sc[5], kk = sc[6];
    const float4 W2v = sc[7], b2v = sc[8], W3a = sc[9], W3b = sc[10];

    int i = blockIdx.x * blockDim.x + threadIdx.x;

    #pragma unroll
    for (int g = 0; g < 2; ++g) {
        // Front-batch 4 independent LDG.128.
        float4 xv[4];
        #pragma unroll
        for (int k = 0; k < 4; ++k) xv[k] = x4[i + (g * 4 + k) * stride];

        #pragma unroll
        for (int k = 0; k < 4; ++k) {
            float4 x = xv[k];

            float u0 = fmaf(r0.x, x.x, fmaf(r0.y, x.y, fmaf(r0.z, x.z, fmaf(r0.w, x.w, bs.x))));
            float u1 = fmaf(r1.x, x.x, fmaf(r1.y, x.y, fmaf(r1.z, x.z, fmaf(r1.w, x.w, bs.y))));
            float u2 = fmaf(r2.x, x.x, fmaf(r2.y, x.y, fmaf(r2.z, x.z, fmaf(r2.w, x.w, bs.z))));
            float u3 = fmaf(r3.x, x.x, fmaf(r3.y, x.y, fmaf(r3.z, x.z, fmaf(r3.w, x.w, bs.w))));

            float e0, e1, e2, e3;
            asm("ex2.approx.f32 %0, %1;" : "=f"(e0) : "f"(u0));
            asm("ex2.approx.f32 %0, %1;" : "=f"(e1) : "f"(u1));
            asm("ex2.approx.f32 %0, %1;" : "=f"(e2) : "f"(u2));
            asm("ex2.approx.f32 %0, %1;" : "=f"(e3) : "f"(u3));

            float d0, d1, d2, d3;
            asm("rcp.approx.f32 %0, %1;" : "=f"(d0) : "f"(1.0f + e0));
            asm("rcp.approx.f32 %0, %1;" : "=f"(d1) : "f"(1.0f + e1));
            asm("rcp.approx.f32 %0, %1;" : "=f"(d2) : "f"(1.0f + e2));
            asm("rcp.approx.f32 %0, %1;" : "=f"(d3) : "f"(1.0f + e3));

            float th0 = fmaf(1.0f - e0, d0, q0.x);
            float th1 = fmaf(1.0f - e1, d1, q0.y);
            float th2 = fmaf(1.0f - e2, d2, q0.z);
            float th3 = fmaf(1.0f - e3, d3, q0.w);

            float s0 = __sinf(th0);
            float s1 = __sinf(th1);
            float c1 = __cosf(th1);
            float c2 = __cosf(th2);
            float c3 = __cosf(th3);

            float z = fmaf(kk.x, c1 * c2 * c3, -kk.y * (s0 * s1));

            float h20 = fmaxf(fmaf(z, W2v.x, b2v.x), 0.f);
            float h21 = fmaxf(fmaf(z, W2v.y, b2v.y), 0.f);
            float h22 = fmaxf(fmaf(z, W2v.z, b2v.z), 0.f);
            float h23 = fmaxf(fmaf(z, W2v.w, b2v.w), 0.f);
            float o0 = fmaf(h20, W3a.x, fmaf(h21, W3a.y, fmaf(h22, W3a.z, fmaf(h23, W3a.w, kk.z))));
            float o1 = fmaf(h20, W3b.x, fmaf(h21, W3b.y, fmaf(h22, W3b.z, fmaf(h23, W3b.w, kk.w))));
            out[i + (g * 4 + k) * stride] = make_float2(o0, o1);
        }
    }
}

extern "C" void kernel_launch(void* const* d_in, const int* in_sizes, int n_in,
                              void* d_out, int out_size) {
    const float* x  = (const float*)d_in[0];
    const float* W1 = (const float*)d_in[1];
    const float* b1 = (const float*)d_in[2];
    const float* qw = (const float*)d_in[3];
    const float* W2 = (const float*)d_in[4];
    const float* b2 = (const float*)d_in[5];
    const float* W3 = (const float*)d_in[6];
    const float* b3 = (const float*)d_in[7];

    int n = in_sizes[0] / 4;    // samples (1048576)
    int stride = n / 8;         // 8 samples per thread
    const int threads = 256;
    const int blocks = stride / threads;   // 512 -> single wave
    qnn_fused<<<blocks, threads>>>((const float4*)x, (float2*)d_out, stride,
                                   W1, b1, qw, W2, b2, W3, b3);
}

// round 10
// speedup vs baseline: 1.0026x; 1.0026x over previous
#include <cuda_runtime.h>

// Fused kernel, parallel per-block prelude, 2 samples/thread (paired layout,
// single STG.128 per thread), grid 2048 for high resident-warp count.
//
// Math (verified rounds 2-3):
//   h_j  = tanh(W1[j,:].x + b1[j]);  th_j = h_j + qw[0,j]
//   z    = K1*cos(th1)cos(th2)cos(th3) - K2*sin(th0)sin(th1)
//          K1 = cos(qw[2,0]),  K2 = sin(qw[2,0])*cos(qw[1,0])*cos(qw[1,1])
//   out  = relu(z*W2 + b2) @ W3^T + b3
//
// tanh(u) = (1-e)*rcp(1+e), e = ex2(-2*log2e*u): sign-correct, clamp-free.

__global__ void __launch_bounds__(256) qnn_fused(
    const float4* __restrict__ x4, float4* __restrict__ out,
    const float* __restrict__ W1, const float* __restrict__ b1,
    const float* __restrict__ qw, const float* __restrict__ W2,
    const float* __restrict__ b2, const float* __restrict__ W3,
    const float* __restrict__ b3)
{
    __shared__ float4 sc[11];
    {
        float* v = reinterpret_cast<float*>(sc);
        const float SC = -2.8853900817779268f;   // -2*log2(e)
        int t = threadIdx.x;
        if (t < 16)      v[t] = SC * W1[t];                 // W1s rows 0..3
        else if (t < 20) v[t] = SC * b1[t - 16];            // b1s
        else if (t < 24) v[t] = qw[t - 20];                 // qw[0,i]
        else if (t == 24) v[24] = __cosf(qw[8]);            // K1
        else if (t == 25) v[25] = __sinf(qw[8]) * __cosf(qw[4]) * __cosf(qw[5]); // K2
        else if (t < 28) v[t] = b3[t - 26];                 // b3
        else if (t < 32) v[t] = W2[t - 28];                 // W2
        else if (t < 36) v[t] = b2[t - 32];                 // b2
        else if (t < 44) v[t] = W3[t - 36];                 // W3 (2x4)
    }
    __syncthreads();

    const float4 r0 = sc[0], r1 = sc[1], r2 = sc[2], r3 = sc[3], bs = sc[4];
    const float4 q0 = sc[5], kk = sc[6];
    const float4 W2v = sc[7], b2v = sc[8], W3a = sc[9], W3b = sc[10];

    int i = blockIdx.x * blockDim.x + threadIdx.x;

    // Two adjacent samples: contiguous 2x LDG.128.
    float4 xa = x4[2 * i];
    float4 xb = x4[2 * i + 1];

    float za, zb;
    #pragma unroll
    for (int k = 0; k < 2; ++k) {
        float4 x = (k == 0) ? xa : xb;

        float u0 = fmaf(r0.x, x.x, fmaf(r0.y, x.y, fmaf(r0.z, x.z, fmaf(r0.w, x.w, bs.x))));
        float u1 = fmaf(r1.x, x.x, fmaf(r1.y, x.y, fmaf(r1.z, x.z, fmaf(r1.w, x.w, bs.y))));
        float u2 = fmaf(r2.x, x.x, fmaf(r2.y, x.y, fmaf(r2.z, x.z, fmaf(r2.w, x.w, bs.z))));
        float u3 = fmaf(r3.x, x.x, fmaf(r3.y, x.y, fmaf(r3.z, x.z, fmaf(r3.w, x.w, bs.w))));

        float e0, e1, e2, e3;
        asm("ex2.approx.f32 %0, %1;" : "=f"(e0) : "f"(u0));
        asm("ex2.approx.f32 %0, %1;" : "=f"(e1) : "f"(u1));
        asm("ex2.approx.f32 %0, %1;" : "=f"(e2) : "f"(u2));
        asm("ex2.approx.f32 %0, %1;" : "=f"(e3) : "f"(u3));

        float d0, d1, d2, d3;
        asm("rcp.approx.f32 %0, %1;" : "=f"(d0) : "f"(1.0f + e0));
        asm("rcp.approx.f32 %0, %1;" : "=f"(d1) : "f"(1.0f + e1));
        asm("rcp.approx.f32 %0, %1;" : "=f"(d2) : "f"(1.0f + e2));
        asm("rcp.approx.f32 %0, %1;" : "=f"(d3) : "f"(1.0f + e3));

        float th0 = fmaf(1.0f - e0, d0, q0.x);
        float th1 = fmaf(1.0f - e1, d1, q0.y);
        float th2 = fmaf(1.0f - e2, d2, q0.z);
        float th3 = fmaf(1.0f - e3, d3, q0.w);

        float s0 = __sinf(th0);
        float s1 = __sinf(th1);
        float c1 = __cosf(th1);
        float c2 = __cosf(th2);
        float c3 = __cosf(th3);

        float z = fmaf(kk.x, c1 * c2 * c3, -kk.y * (s0 * s1));
        if (k == 0) za = z; else zb = z;
    }

    // post-MLP for both samples, packed into one float4 store.
    float4 o;
    {
        float h20 = fmaxf(fmaf(za, W2v.x, b2v.x), 0.f);
        float h21 = fmaxf(fmaf(za, W2v.y, b2v.y), 0.f);
        float h22 = fmaxf(fmaf(za, W2v.z, b2v.z), 0.f);
        float h23 = fmaxf(fmaf(za, W2v.w, b2v.w), 0.f);
        o.x = fmaf(h20, W3a.x, fmaf(h21, W3a.y, fmaf(h22, W3a.z, fmaf(h23, W3a.w, kk.z))));
        o.y = fmaf(h20, W3b.x, fmaf(h21, W3b.y, fmaf(h22, W3b.z, fmaf(h23, W3b.w, kk.w))));
    }
    {
        float h20 = fmaxf(fmaf(zb, W2v.x, b2v.x), 0.f);
        float h21 = fmaxf(fmaf(zb, W2v.y, b2v.y), 0.f);
        float h22 = fmaxf(fmaf(zb, W2v.z, b2v.z), 0.f);
        float h23 = fmaxf(fmaf(zb, W2v.w, b2v.w), 0.f);
        o.z = fmaf(h20, W3a.x, fmaf(h21, W3a.y, fmaf(h22, W3a.z, fmaf(h23, W3a.w, kk.z))));
        o.w = fmaf(h20, W3b.x, fmaf(h21, W3b.y, fmaf(h22, W3b.z, fmaf(h23, W3b.w, kk.w))));
    }
    out[i] = o;
}

extern "C" void kernel_launch(void* const* d_in, const int* in_sizes, int n_in,
                              void* d_out, int out_size) {
    const float* x  = (const float*)d_in[0];
    const float* W1 = (const float*)d_in[1];
    const float* b1 = (const float*)d_in[2];
    const float* qw = (const float*)d_in[3];
    const float* W2 = (const float*)d_in[4];
    const float* b2 = (const float*)d_in[5];
    const float* W3 = (const float*)d_in[6];
    const float* b3 = (const float*)d_in[7];

    int n2 = in_sizes[0] / 8;   // thread count = samples/2 (524288)
    const int threads = 256;
    const int blocks = n2 / threads;   // 2048
    qnn_fused<<<blocks, threads>>>((const float4*)x, (float4*)d_out,
                                   W1, b1, qw, W2, b2, W3, b3);
}

// round 11
// speedup vs baseline: 1.0079x; 1.0052x over previous
#include <cuda_runtime.h>

// Fused kernel. x-loads issued BEFORE the prelude barrier so DRAM latency
// overlaps the shared-memory constant build. 4 samples/thread, phase-strided
// (fully coalesced), grid 1024.
//
// Math (verified rounds 2-3):
//   h_j  = tanh(W1[j,:].x + b1[j]);  th_j = h_j + qw[0,j]
//   z    = K1*cos(th1)cos(th2)cos(th3) - K2*sin(th0)sin(th1)
//          K1 = cos(qw[2,0]),  K2 = sin(qw[2,0])*cos(qw[1,0])*cos(qw[1,1])
//   out  = relu(z*W2 + b2) @ W3^T + b3
//
// tanh(u) = (1-e)*rcp(1+e), e = ex2(-2*log2e*u): sign-correct, clamp-free.

__global__ void __launch_bounds__(256) qnn_fused(
    const float4* __restrict__ x4, float2* __restrict__ out, int stride,
    const float* __restrict__ W1, const float* __restrict__ b1,
    const float* __restrict__ qw, const float* __restrict__ W2,
    const float* __restrict__ b2, const float* __restrict__ W3,
    const float* __restrict__ b3)
{
    __shared__ float4 sc[11];

    const int i = blockIdx.x * blockDim.x + threadIdx.x;

    // ---- Front-batched sample loads, issued BEFORE the barrier. ----
    float4 xv0 = x4[i];
    float4 xv1 = x4[i + stride];
    float4 xv2 = x4[i + 2 * stride];
    float4 xv3 = x4[i + 3 * stride];

    {
        float* v = reinterpret_cast<float*>(sc);
        const float SC = -2.8853900817779268f;   // -2*log2(e)
        int t = threadIdx.x;
        if (t < 16)      v[t] = SC * W1[t];                 // W1s rows 0..3
        else if (t < 20) v[t] = SC * b1[t - 16];            // b1s
        else if (t < 24) v[t] = qw[t - 20];                 // qw[0,i]
        else if (t == 24) v[24] = __cosf(qw[8]);            // K1
        else if (t == 25) v[25] = __sinf(qw[8]) * __cosf(qw[4]) * __cosf(qw[5]); // K2
        else if (t < 28) v[t] = b3[t - 26];                 // b3
        else if (t < 32) v[t] = W2[t - 28];                 // W2
        else if (t < 36) v[t] = b2[t - 32];                 // b2
        else if (t < 44) v[t] = W3[t - 36];                 // W3 (2x4)
    }
    __syncthreads();

    const float4 r0 = sc[0], r1 = sc[1], r2 = sc[2], r3 = sc[3], bs = sc[4];
    const float4 q0 = sc[5], kk = sc[6];
    const float4 W2v = sc[7], b2v = sc[8], W3a = sc[9], W3b = sc[10];

    float4 xv[4] = {xv0, xv1, xv2, xv3};

    #pragma unroll
    for (int k = 0; k < 4; ++k) {
        float4 x = xv[k];

        float u0 = fmaf(r0.x, x.x, fmaf(r0.y, x.y, fmaf(r0.z, x.z, fmaf(r0.w, x.w, bs.x))));
        float u1 = fmaf(r1.x, x.x, fmaf(r1.y, x.y, fmaf(r1.z, x.z, fmaf(r1.w, x.w, bs.y))));
        float u2 = fmaf(r2.x, x.x, fmaf(r2.y, x.y, fmaf(r2.z, x.z, fmaf(r2.w, x.w, bs.z))));
        float u3 = fmaf(r3.x, x.x, fmaf(r3.y, x.y, fmaf(r3.z, x.z, fmaf(r3.w, x.w, bs.w))));

        float e0, e1, e2, e3;
        asm("ex2.approx.f32 %0, %1;" : "=f"(e0) : "f"(u0));
        asm("ex2.approx.f32 %0, %1;" : "=f"(e1) : "f"(u1));
        asm("ex2.approx.f32 %0, %1;" : "=f"(e2) : "f"(u2));
        asm("ex2.approx.f32 %0, %1;" : "=f"(e3) : "f"(u3));

        float d0, d1, d2, d3;
        asm("rcp.approx.f32 %0, %1;" : "=f"(d0) : "f"(1.0f + e0));
        asm("rcp.approx.f32 %0, %1;" : "=f"(d1) : "f"(1.0f + e1));
        asm("rcp.approx.f32 %0, %1;" : "=f"(d2) : "f"(1.0f + e2));
        asm("rcp.approx.f32 %0, %1;" : "=f"(d3) : "f"(1.0f + e3));

        // th = (1-e)*d + q  ==  (d - e*d) + q
        float th0 = fmaf(-e0, d0, d0) + q0.x;
        float th1 = fmaf(-e1, d1, d1) + q0.y;
        float th2 = fmaf(-e2, d2, d2) + q0.z;
        float th3 = fmaf(-e3, d3, d3) + q0.w;

        float s0 = __sinf(th0);
        float s1 = __sinf(th1);
        float c1 = __cosf(th1);
        float c2 = __cosf(th2);
        float c3 = __cosf(th3);

        float z = fmaf(kk.x, c1 * c2 * c3, -kk.y * (s0 * s1));

        float h20 = fmaxf(fmaf(z, W2v.x, b2v.x), 0.f);
        float h21 = fmaxf(fmaf(z, W2v.y, b2v.y), 0.f);
        float h22 = fmaxf(fmaf(z, W2v.z, b2v.z), 0.f);
        float h23 = fmaxf(fmaf(z, W2v.w, b2v.w), 0.f);
        float o0 = fmaf(h20, W3a.x, fmaf(h21, W3a.y, fmaf(h22, W3a.z, fmaf(h23, W3a.w, kk.z))));
        float o1 = fmaf(h20, W3b.x, fmaf(h21, W3b.y, fmaf(h22, W3b.z, fmaf(h23, W3b.w, kk.w))));
        out[i + k * stride] = make_float2(o0, o1);
    }
}

extern "C" void kernel_launch(void* const* d_in, const int* in_sizes, int n_in,
                              void* d_out, int out_size) {
    const float* x  = (const float*)d_in[0];
    const float* W1 = (const float*)d_in[1];
    const float* b1 = (const float*)d_in[2];
    const float* qw = (const float*)d_in[3];
    const float* W2 = (const float*)d_in[4];
    const float* b2 = (const float*)d_in[5];
    const float* W3 = (const float*)d_in[6];
    const float* b3 = (const float*)d_in[7];

    int n = in_sizes[0] / 4;    // samples (1048576)
    int stride = n / 4;         // 4 samples per thread
    const int threads = 256;
    const int blocks = stride / threads;   // 1024
    qnn_fused<<<blocks, threads>>>((const float4*)x, (float2*)d_out, stride,
                                   W1, b1, qw, W2, b2, W3, b3);
}